// round 1
// baseline (speedup 1.0000x reference)
#include <cuda_runtime.h>

#define DT    0.01f
#define SIGMA 10.0f
#define RHO   28.0f
#define BETA  (8.0f / 3.0f)

__device__ __forceinline__ void lorenz(float x, float y, float z,
                                       float& dx, float& dy, float& dz) {
    dx = SIGMA * (y - x);
    dy = fmaf(x, RHO - z, -y);
    dz = fmaf(x, y, -BETA * z);
}

__device__ __forceinline__ void rk4_step(float& x, float& y, float& z) {
    float k1x, k1y, k1z, k2x, k2y, k2z, k3x, k3y, k3z, k4x, k4y, k4z;
    lorenz(x, y, z, k1x, k1y, k1z);
    lorenz(fmaf(0.5f * DT, k1x, x), fmaf(0.5f * DT, k1y, y), fmaf(0.5f * DT, k1z, z),
           k2x, k2y, k2z);
    lorenz(fmaf(0.5f * DT, k2x, x), fmaf(0.5f * DT, k2y, y), fmaf(0.5f * DT, k2z, z),
           k3x, k3y, k3z);
    lorenz(fmaf(DT, k3x, x), fmaf(DT, k3y, y), fmaf(DT, k3z, z),
           k4x, k4y, k4z);
    const float c = DT / 6.0f;
    x = fmaf(c, k1x + 2.0f * k2x + 2.0f * k3x + k4x, x);
    y = fmaf(c, k1y + 2.0f * k2y + 2.0f * k3y + k4y, y);
    z = fmaf(c, k1z + 2.0f * k2z + 2.0f * k3z + k4z, z);
}

// Each thread handles 4 states = 12 floats = 3 float4 loads/stores (coalesced 128-bit).
__global__ void __launch_bounds__(256)
lorenz_rk4_kernel(const float4* __restrict__ in, float4* __restrict__ out, int n_vec4_groups) {
    int i = blockIdx.x * blockDim.x + threadIdx.x;
    if (i >= n_vec4_groups) return;

    float4 a = in[3 * i + 0];
    float4 b = in[3 * i + 1];
    float4 c = in[3 * i + 2];

    // states: (a.x,a.y,a.z) (a.w,b.x,b.y) (b.z,b.w,c.x) (c.y,c.z,c.w)
    rk4_step(a.x, a.y, a.z);
    rk4_step(a.w, b.x, b.y);
    rk4_step(b.z, b.w, c.x);
    rk4_step(c.y, c.z, c.w);

    out[3 * i + 0] = a;
    out[3 * i + 1] = b;
    out[3 * i + 2] = c;
}

// Tail path: scalar per-state for leftover states (n % 4 != 0 case).
__global__ void lorenz_rk4_tail_kernel(const float* __restrict__ in, float* __restrict__ out,
                                       int start_state, int n_states) {
    int s = start_state + blockIdx.x * blockDim.x + threadIdx.x;
    if (s >= n_states) return;
    float x = in[3 * s + 0], y = in[3 * s + 1], z = in[3 * s + 2];
    rk4_step(x, y, z);
    out[3 * s + 0] = x;
    out[3 * s + 1] = y;
    out[3 * s + 2] = z;
}

extern "C" void kernel_launch(void* const* d_in, const int* in_sizes, int n_in,
                              void* d_out, int out_size) {
    const float* x = (const float*)d_in[0];
    float* out = (float*)d_out;

    int n_states = in_sizes[0] / 3;      // 8,000,000
    int n_groups = n_states / 4;         // states handled 4-at-a-time
    int tail_start = n_groups * 4;

    if (n_groups > 0) {
        int threads = 256;
        int blocks = (n_groups + threads - 1) / threads;
        lorenz_rk4_kernel<<<blocks, threads>>>((const float4*)x, (float4*)out, n_groups);
    }
    if (tail_start < n_states) {
        int rem = n_states - tail_start;
        int threads = 256;
        int blocks = (rem + threads - 1) / threads;
        lorenz_rk4_tail_kernel<<<blocks, threads>>>(x, out, tail_start, n_states);
    }
}